// round 9
// baseline (speedup 1.0000x reference)
#include <cuda_runtime.h>
#include <cuda_fp16.h>
#include <cuda_bf16.h>

#define N_NODES 100000
#define N_EDGES 3200000
#define IN_CH   128
#define HID     16

#define SCAN_TB 1024
#define NBLK    ((N_NODES + SCAN_TB - 1) / SCAN_TB)   // 98

// ---------------- device scratch (no allocation allowed) ----------------
__device__ __align__(16) int    g_cnt [N_NODES];
__device__ __align__(16) int    g_off [N_NODES];
__device__ __align__(16) int    g_offA[N_NODES];
__device__ __align__(16) int    g_fill[N_NODES];
__device__ __align__(16) int    g_bsum[NBLK];
__device__ __align__(16) int    g_bpre[NBLK];
__device__ int                  g_done;
__device__ __align__(16) int    g_adj [N_EDGES];
__device__ __align__(16) float  g_dinv[N_NODES];
__device__ __align__(16) __half g_hs  [N_NODES * HID];  // layer-1 messages (fp16)
__device__ __align__(16) __half g_hs2 [N_NODES * HID];  // layer-2 messages (fp16)

__device__ __forceinline__ unsigned h2u(__half2 h) {
    return *reinterpret_cast<unsigned*>(&h);
}

// ---------------- CSR build (compact; R6-proven) ----------------

__global__ void k_zero(int n4) {
    int i = blockIdx.x * blockDim.x + threadIdx.x;
    if (i < n4) ((int4*)g_cnt)[i] = make_int4(0, 0, 0, 0);
    if (i == 0) g_done = 0;
}

__global__ void k_count(const int* __restrict__ col, int e4) {
    int i = blockIdx.x * blockDim.x + threadIdx.x;
    if (i >= e4) return;
    int4 c = __ldg(&((const int4*)col)[i]);
    atomicAdd(&g_cnt[c.x], 1);
    atomicAdd(&g_cnt[c.y], 1);
    atomicAdd(&g_cnt[c.z], 1);
    atomicAdd(&g_cnt[c.w], 1);
}

__global__ void k_scanA(int n, int nb) {
    __shared__ int s[SCAN_TB];
    __shared__ int is_last;
    int i = blockIdx.x * SCAN_TB + threadIdx.x;
    int v = (i < n) ? g_cnt[i] : 0;
    s[threadIdx.x] = v;
    __syncthreads();
    for (int d = 1; d < SCAN_TB; d <<= 1) {
        int t = (threadIdx.x >= d) ? s[threadIdx.x - d] : 0;
        __syncthreads();
        s[threadIdx.x] += t;
        __syncthreads();
    }
    if (i < n) g_offA[i] = s[threadIdx.x] - v;
    if (threadIdx.x == SCAN_TB - 1) g_bsum[blockIdx.x] = s[SCAN_TB - 1];

    __threadfence();
    if (threadIdx.x == 0) is_last = (atomicAdd(&g_done, 1) == nb - 1);
    __syncthreads();
    if (!is_last) return;

    __threadfence();
    int b = threadIdx.x;
    int bv = (b < nb) ? g_bsum[b] : 0;
    s[b] = bv;
    __syncthreads();
    for (int d = 1; d < SCAN_TB; d <<= 1) {
        int t = (b >= d) ? s[b - d] : 0;
        __syncthreads();
        s[b] += t;
        __syncthreads();
    }
    if (b < nb) g_bpre[b] = s[b] - bv;
}

__global__ void k_scanC(int n) {
    int i = blockIdx.x * blockDim.x + threadIdx.x;
    if (i >= n) return;
    int off = g_offA[i] + g_bpre[i >> 10];
    g_off[i]  = off;
    g_fill[i] = off;
    g_dinv[i] = rsqrtf((float)(g_cnt[i] + 1));
}

__global__ void k_fill(const int* __restrict__ row, const int* __restrict__ col, int e4) {
    int i = blockIdx.x * blockDim.x + threadIdx.x;
    if (i >= e4) return;
    int4 r = __ldg(&((const int4*)row)[i]);
    int4 c = __ldg(&((const int4*)col)[i]);
    g_adj[atomicAdd(&g_fill[c.x], 1)] = r.x;
    g_adj[atomicAdd(&g_fill[c.y], 1)] = r.y;
    g_adj[atomicAdd(&g_fill[c.z], 1)] = r.z;
    g_adj[atomicAdd(&g_fill[c.w], 1)] = r.w;
}

// ---------------- compute ----------------

// hs = fp16( dinv * (x @ W1) ), 4 lanes/node, coalesced x reads; pair-layout output
__global__ void k_mm1(const float* __restrict__ x, const float* __restrict__ W1, int n) {
    __shared__ float4 Ws[IN_CH * HID / 4];   // W1[k][j], float4 over j
    for (int t = threadIdx.x; t < IN_CH * HID / 4; t += blockDim.x)
        Ws[t] = ((const float4*)W1)[t];
    __syncthreads();

    int gid = blockIdx.x * blockDim.x + threadIdx.x;
    int i = gid >> 2;
    int q = gid & 3;
    if (i >= n) return;

    float a[HID];
#pragma unroll
    for (int j = 0; j < HID; j++) a[j] = 0.0f;

    // lane q handles k in [32q, 32q+32): warp reads 4KB coalesced
    const float4* xr = (const float4*)(x + (size_t)i * IN_CH + q * 32);
#pragma unroll
    for (int m = 0; m < 8; m++) {
        float4 xv = xr[m];
        float xs[4] = {xv.x, xv.y, xv.z, xv.w};
        int kbase = q * 32 + m * 4;
#pragma unroll
        for (int r = 0; r < 4; r++) {
            const float4* w = &Ws[(kbase + r) * 4];
#pragma unroll
            for (int t = 0; t < 4; t++) {
                float4 wv = w[t];
                a[4 * t + 0] += xs[r] * wv.x;
                a[4 * t + 1] += xs[r] * wv.y;
                a[4 * t + 2] += xs[r] * wv.z;
                a[4 * t + 3] += xs[r] * wv.w;
            }
        }
    }

    // allreduce a[16] across the quad (every lane ends with the full sum)
    unsigned lane = threadIdx.x & 31u;
    unsigned qmask = 0xFu << (lane & ~3u);
#pragma unroll
    for (int j = 0; j < HID; j++) {
        a[j] += __shfl_xor_sync(qmask, a[j], 1, 4);
        a[j] += __shfl_xor_sync(qmask, a[j], 2, 4);
    }

    float d = g_dinv[i];
    // pair layout: lane q<2 writes 16B half q (features 8q..8q+8)
    if (q < 2) {
        uint4 pack;
        __half2 t0 = __floats2half2_rn(d * a[8 * q + 0], d * a[8 * q + 1]);
        __half2 t1 = __floats2half2_rn(d * a[8 * q + 2], d * a[8 * q + 3]);
        __half2 t2 = __floats2half2_rn(d * a[8 * q + 4], d * a[8 * q + 5]);
        __half2 t3 = __floats2half2_rn(d * a[8 * q + 6], d * a[8 * q + 7]);
        pack.x = h2u(t0); pack.y = h2u(t1); pack.z = h2u(t2); pack.w = h2u(t3);
        ((uint4*)g_hs)[(size_t)i * 2 + q] = pack;
    }
}

// accumulate one fp16x8 message into fp32 acc[8]
__device__ __forceinline__ void acc_msg(float* a, uint4 v) {
    const __half2* h = reinterpret_cast<const __half2*>(&v);
#pragma unroll
    for (int t = 0; t < 4; t++) {
        float2 f = __half22float2(h[t]);
        a[2 * t]     += f.x;
        a[2 * t + 1] += f.y;
    }
}

// pair gather: lane p owns features [8p,8p+8); paired lanes hit the same 32B sector
__device__ __forceinline__ void pair_gather(const uint4* __restrict__ S,
                                            float* a, int k, int end, int p) {
    if (k + 8 <= end) {
        int r[8];
#pragma unroll
        for (int u = 0; u < 8; u++) r[u] = __ldg(&g_adj[k + u]);
        k += 8;
        while (k + 8 <= end) {
            int rn[8];
#pragma unroll
            for (int u = 0; u < 8; u++) rn[u] = __ldg(&g_adj[k + u]);
            uint4 v[8];
#pragma unroll
            for (int u = 0; u < 8; u++) v[u] = S[(size_t)r[u] * 2 + p];
#pragma unroll
            for (int u = 0; u < 8; u++) acc_msg(a, v[u]);
#pragma unroll
            for (int u = 0; u < 8; u++) r[u] = rn[u];
            k += 8;
        }
        uint4 v[8];
#pragma unroll
        for (int u = 0; u < 8; u++) v[u] = S[(size_t)r[u] * 2 + p];
#pragma unroll
        for (int u = 0; u < 8; u++) acc_msg(a, v[u]);
    }
    for (; k < end; k++) {
        uint4 v = S[(size_t)__ldg(&g_adj[k]) * 2 + p];
        acc_msg(a, v);
    }
}

// epilogue for one node in gather_mid
__device__ __forceinline__ void mid_epilogue(const float* Ws, const float* b1,
                                             const float* a, int i, int p,
                                             unsigned pm) {
    float d = g_dinv[i];
    float h8[8];
#pragma unroll
    for (int j = 0; j < 8; j++)
        h8[j] = fmaxf(d * a[j] + __ldg(&b1[p * 8 + j]), 0.0f);

    float hall[HID];
#pragma unroll
    for (int j = 0; j < 8; j++) hall[p * 8 + j] = h8[j];
#pragma unroll
    for (int j = 0; j < 8; j++)
        hall[(p ^ 1) * 8 + j] = __shfl_xor_sync(pm, h8[j], 1, 2);

    float t[8];
#pragma unroll
    for (int j = 0; j < 8; j++) t[j] = 0.0f;
#pragma unroll
    for (int k = 0; k < HID; k++) {
        float hk = hall[k];
        const float* w = &Ws[k * HID + p * 8];
#pragma unroll
        for (int j = 0; j < 8; j++) t[j] += hk * w[j];
    }

    uint4 pack;
    __half2 o0 = __floats2half2_rn(d * t[0], d * t[1]);
    __half2 o1 = __floats2half2_rn(d * t[2], d * t[3]);
    __half2 o2 = __floats2half2_rn(d * t[4], d * t[5]);
    __half2 o3 = __floats2half2_rn(d * t[6], d * t[7]);
    pack.x = h2u(o0); pack.y = h2u(o1); pack.z = h2u(o2); pack.w = h2u(o3);
    ((uint4*)g_hs2)[(size_t)i * 2 + p] = pack;
}

// gather layer-1 + fused transform; two nodes per thread (i, i+half) for balance
__global__ void k_gather_mid(const float* __restrict__ W2, const float* __restrict__ b1,
                             int n, int half) {
    __shared__ float Ws[HID * HID];
    if (threadIdx.x < HID * HID / 4)
        ((float4*)Ws)[threadIdx.x] = ((const float4*)W2)[threadIdx.x];
    __syncthreads();

    int gid = blockIdx.x * blockDim.x + threadIdx.x;
    int t = gid >> 1;
    int p = gid & 1;
    if (t >= half) return;
    int i0 = t;
    int i1 = t + half;

    unsigned lane = threadIdx.x & 31u;
    unsigned pm = 0x3u << (lane & ~1u);
    const uint4* S = (const uint4*)g_hs;

    float a0[8], a1[8];
#pragma unroll
    for (int j = 0; j < 8; j++) { a0[j] = 0.0f; a1[j] = 0.0f; }

    acc_msg(a0, S[(size_t)i0 * 2 + p]);
    int off0 = g_off[i0];
    pair_gather(S, a0, off0, off0 + g_cnt[i0], p);

    acc_msg(a1, S[(size_t)i1 * 2 + p]);
    int off1 = g_off[i1];
    pair_gather(S, a1, off1, off1 + g_cnt[i1], p);

    mid_epilogue(Ws, b1, a0, i0, p, pm);
    mid_epilogue(Ws, b1, a1, i1, p, pm);
}

// readout epilogue for one node
__device__ __forceinline__ void final_epilogue(const float* __restrict__ b2,
                                               const float* __restrict__ Wl,
                                               const float* __restrict__ bl,
                                               float* __restrict__ out,
                                               const float* a, int i, int p,
                                               unsigned pm) {
    float d = g_dinv[i];
    float s = 0.0f;
#pragma unroll
    for (int j = 0; j < 8; j++)
        s += fmaxf(d * a[j] + __ldg(&b2[p * 8 + j]), 0.0f) * __ldg(&Wl[p * 8 + j]);
    s += __shfl_xor_sync(pm, s, 1, 2);
    if (p == 0) out[i] = s + __ldg(bl);
}

// gather layer-2 + fused readout; two nodes per thread
__global__ void k_gather_final(const float* __restrict__ b2, const float* __restrict__ Wl,
                               const float* __restrict__ bl, float* __restrict__ out,
                               int n, int half) {
    int gid = blockIdx.x * blockDim.x + threadIdx.x;
    int t = gid >> 1;
    int p = gid & 1;
    if (t >= half) return;
    int i0 = t;
    int i1 = t + half;

    unsigned lane = threadIdx.x & 31u;
    unsigned pm = 0x3u << (lane & ~1u);
    const uint4* S = (const uint4*)g_hs2;

    float a0[8], a1[8];
#pragma unroll
    for (int j = 0; j < 8; j++) { a0[j] = 0.0f; a1[j] = 0.0f; }

    acc_msg(a0, S[(size_t)i0 * 2 + p]);
    int off0 = g_off[i0];
    pair_gather(S, a0, off0, off0 + g_cnt[i0], p);

    acc_msg(a1, S[(size_t)i1 * 2 + p]);
    int off1 = g_off[i1];
    pair_gather(S, a1, off1, off1 + g_cnt[i1], p);

    final_epilogue(b2, Wl, bl, out, a0, i0, p, pm);
    final_epilogue(b2, Wl, bl, out, a1, i1, p, pm);
}

// ---------------- launch ----------------

extern "C" void kernel_launch(void* const* d_in, const int* in_sizes, int n_in,
                              void* d_out, int out_size) {
    const float* x   = (const float*)d_in[0];
    const int*   ei  = (const int*)  d_in[1];
    const float* W1  = (const float*)d_in[2];
    const float* b1  = (const float*)d_in[3];
    const float* W2  = (const float*)d_in[4];
    const float* b2  = (const float*)d_in[5];
    const float* Wl  = (const float*)d_in[6];
    const float* bl  = (const float*)d_in[7];
    float* out = (float*)d_out;

    const int n = in_sizes[0] / IN_CH;   // 100000
    const int e = in_sizes[1] / 2;       // 3200000
    const int* row = ei;
    const int* col = ei + e;

    const int TB   = 256;
    const int gn   = (n + TB - 1) / TB;
    const int n4   = n / 4;
    const int e4   = e / 4;
    const int half = n / 2;              // 50000 (n even)
    const int gp   = (half * 2 + TB - 1) / TB;
    const int gq   = (n * 4 + TB - 1) / TB;
    const int nb   = (n + SCAN_TB - 1) / SCAN_TB;

    // CSR build
    k_zero <<<(n4 + TB - 1) / TB, TB>>>(n4);
    k_count<<<(e4 + TB - 1) / TB, TB>>>(col, e4);
    k_scanA<<<nb,  SCAN_TB>>>(n, nb);
    k_scanC<<<gn,  TB>>>(n);
    k_fill <<<(e4 + TB - 1) / TB, TB>>>(row, col, e4);

    // layer 1 (+ fused layer-2 transform)
    k_mm1       <<<gq, TB>>>(x, W1, n);
    k_gather_mid<<<gp, TB>>>(W2, b1, n, half);

    // layer 2 (+ fused readout)
    k_gather_final<<<gp, TB>>>(b2, Wl, bl, out, n, half);
}

// round 10
// speedup vs baseline: 1.7822x; 1.7822x over previous
#include <cuda_runtime.h>
#include <cuda_fp16.h>
#include <cuda_bf16.h>

#define N_NODES 100000
#define N_EDGES 3200000
#define IN_CH   128
#define HID     16
#define MAXD    64            // fixed adjacency stride; overflow handled exactly
#define OVF_MAX 4096

// ---------------- device scratch (no allocation allowed) ----------------
__device__ __align__(16) int    g_cnt[N_NODES];
__device__ __align__(16) int    g_adj[N_NODES * MAXD];   // 25.6 MB fixed-stride adjacency
__device__ int                  g_ovf_cnt;
__device__ __align__(16) int    g_ovf[2 * OVF_MAX];      // (col,row) overflow pairs
__device__ __align__(16) __half g_hs [N_NODES * HID];    // layer-1 messages (fp16)
__device__ __align__(16) __half g_hs2[N_NODES * HID];    // layer-2 messages (fp16)

__device__ __forceinline__ unsigned h2u(__half2 h) {
    return *reinterpret_cast<unsigned*>(&h);
}

// ---------------- build ----------------

__global__ void k_zero(int n4) {
    int i = blockIdx.x * blockDim.x + threadIdx.x;
    if (i < n4) ((int4*)g_cnt)[i] = make_int4(0, 0, 0, 0);
    if (i == 0) g_ovf_cnt = 0;
}

// single-pass adjacency build; atomic return value doubles as degree histogram
__global__ void k_build(const int* __restrict__ row, const int* __restrict__ col, int e4) {
    int i = blockIdx.x * blockDim.x + threadIdx.x;
    if (i >= e4) return;
    int4 r = __ldg(&((const int4*)row)[i]);
    int4 c = __ldg(&((const int4*)col)[i]);
#pragma unroll
    for (int u = 0; u < 4; u++) {
        int cc = (u == 0) ? c.x : (u == 1) ? c.y : (u == 2) ? c.z : c.w;
        int rr = (u == 0) ? r.x : (u == 1) ? r.y : (u == 2) ? r.z : r.w;
        int p = atomicAdd(&g_cnt[cc], 1);
        if (p < MAXD) {
            g_adj[(cc << 6) + p] = rr;
        } else {
            int o = atomicAdd(&g_ovf_cnt, 1);
            if (o < OVF_MAX) { g_ovf[2 * o] = cc; g_ovf[2 * o + 1] = rr; }
        }
    }
}

// ---------------- compute (R6-proven kernels, dinv on the fly) ----------------

// hs = fp16( dinv * (x @ W1) )   — R6 version (broadcast smem reads, no conflicts)
__global__ void k_mm1(const float* __restrict__ x, const float* __restrict__ W1, int n) {
    __shared__ float4 Ws[IN_CH * HID / 4];
    for (int t = threadIdx.x; t < IN_CH * HID / 4; t += blockDim.x)
        Ws[t] = ((const float4*)W1)[t];
    __syncthreads();

    int i = blockIdx.x * blockDim.x + threadIdx.x;
    if (i >= n) return;

    float a[HID];
#pragma unroll
    for (int j = 0; j < HID; j++) a[j] = 0.0f;

    const float4* xr = (const float4*)(x + (size_t)i * IN_CH);
#pragma unroll 8
    for (int k4 = 0; k4 < IN_CH / 4; k4++) {
        float4 xv = xr[k4];
        float xs[4] = {xv.x, xv.y, xv.z, xv.w};
#pragma unroll
        for (int r = 0; r < 4; r++) {
            const float4* w = &Ws[(k4 * 4 + r) * 4];
#pragma unroll
            for (int q = 0; q < 4; q++) {
                float4 wv = w[q];
                a[4 * q + 0] += xs[r] * wv.x;
                a[4 * q + 1] += xs[r] * wv.y;
                a[4 * q + 2] += xs[r] * wv.z;
                a[4 * q + 3] += xs[r] * wv.w;
            }
        }
    }

    float d = rsqrtf((float)(g_cnt[i] + 1));
    uint4 pack[2];
    __half2* hp = (__half2*)pack;
#pragma unroll
    for (int j = 0; j < 8; j++)
        hp[j] = __floats2half2_rn(d * a[2 * j], d * a[2 * j + 1]);
    ((uint4*)g_hs)[(size_t)i * 2 + 0] = pack[0];
    ((uint4*)g_hs)[(size_t)i * 2 + 1] = pack[1];
}

// accumulate one fp16x8 message into fp32 acc[8]
__device__ __forceinline__ void acc_msg(float* a, uint4 v) {
    const __half2* h = reinterpret_cast<const __half2*>(&v);
#pragma unroll
    for (int t = 0; t < 4; t++) {
        float2 f = __half22float2(h[t]);
        a[2 * t]     += f.x;
        a[2 * t + 1] += f.y;
    }
}

// pair gather over fixed-stride adjacency row (R6 loop structure)
__device__ __forceinline__ void pair_gather(const uint4* __restrict__ S,
                                            float* a, const int* __restrict__ adj,
                                            int cn, int p) {
    int k = 0;
    if (k + 8 <= cn) {
        int r[8];
#pragma unroll
        for (int u = 0; u < 8; u++) r[u] = __ldg(&adj[k + u]);
        k += 8;
        while (k + 8 <= cn) {
            int rn[8];
#pragma unroll
            for (int u = 0; u < 8; u++) rn[u] = __ldg(&adj[k + u]);
            uint4 v[8];
#pragma unroll
            for (int u = 0; u < 8; u++) v[u] = S[(size_t)r[u] * 2 + p];
#pragma unroll
            for (int u = 0; u < 8; u++) acc_msg(a, v[u]);
#pragma unroll
            for (int u = 0; u < 8; u++) r[u] = rn[u];
            k += 8;
        }
        uint4 v[8];
#pragma unroll
        for (int u = 0; u < 8; u++) v[u] = S[(size_t)r[u] * 2 + p];
#pragma unroll
        for (int u = 0; u < 8; u++) acc_msg(a, v[u]);
    }
    for (; k < cn; k++) {
        uint4 v = S[(size_t)__ldg(&adj[k]) * 2 + p];
        acc_msg(a, v);
    }
}

// exact overflow fixup: nodes with cnt > MAXD scan the (≈empty) overflow list
__device__ __forceinline__ void ovf_fixup(const uint4* __restrict__ S,
                                          float* a, int i, int p) {
    int no = min(g_ovf_cnt, OVF_MAX);
    for (int o = 0; o < no; o++) {
        if (g_ovf[2 * o] == i) {
            uint4 v = S[(size_t)g_ovf[2 * o + 1] * 2 + p];
            acc_msg(a, v);
        }
    }
}

// gather layer-1 + fused: h1 = relu(d*a + b1); hs2 = fp16(d*(h1 @ W2))
__global__ void k_gather_mid(const float* __restrict__ W2, const float* __restrict__ b1, int n) {
    __shared__ float Ws[HID * HID];
    if (threadIdx.x < HID * HID / 4)
        ((float4*)Ws)[threadIdx.x] = ((const float4*)W2)[threadIdx.x];
    __syncthreads();

    int gid = blockIdx.x * blockDim.x + threadIdx.x;
    int i = gid >> 1;
    int p = gid & 1;
    if (i >= n) return;

    const uint4* S = (const uint4*)g_hs;
    float a[8];
#pragma unroll
    for (int j = 0; j < 8; j++) a[j] = 0.0f;
    acc_msg(a, S[(size_t)i * 2 + p]);                 // self-loop seed
    int cnt = g_cnt[i];
    int cn  = min(cnt, MAXD);
    pair_gather(S, a, &g_adj[(size_t)i << 6], cn, p);
    if (cnt > MAXD) ovf_fixup(S, a, i, p);

    float d = rsqrtf((float)(cnt + 1));
    float h8[8];
    const float* bb = b1 + p * 8;
#pragma unroll
    for (int j = 0; j < 8; j++)
        h8[j] = fmaxf(d * a[j] + __ldg(&bb[j]), 0.0f);

    unsigned lane = threadIdx.x & 31u;
    unsigned pm = 0x3u << (lane & ~1u);
    float hall[HID];
#pragma unroll
    for (int j = 0; j < 8; j++) hall[p * 8 + j] = h8[j];
#pragma unroll
    for (int j = 0; j < 8; j++)
        hall[(p ^ 1) * 8 + j] = __shfl_xor_sync(pm, h8[j], 1, 2);

    float t[8];
#pragma unroll
    for (int j = 0; j < 8; j++) t[j] = 0.0f;
#pragma unroll
    for (int k = 0; k < HID; k++) {
        float hk = hall[k];
        const float* w = &Ws[k * HID + p * 8];
#pragma unroll
        for (int j = 0; j < 8; j++) t[j] += hk * w[j];
    }

    uint4 pack;
    __half2* hp = (__half2*)&pack;
#pragma unroll
    for (int j = 0; j < 4; j++)
        hp[j] = __floats2half2_rn(d * t[2 * j], d * t[2 * j + 1]);
    ((uint4*)g_hs2)[(size_t)i * 2 + p] = pack;
}

// gather layer-2 + fused readout: out = relu(d*a + b2) . Wl + bl
__global__ void k_gather_final(const float* __restrict__ b2, const float* __restrict__ Wl,
                               const float* __restrict__ bl, float* __restrict__ out, int n) {
    int gid = blockIdx.x * blockDim.x + threadIdx.x;
    int i = gid >> 1;
    int p = gid & 1;
    if (i >= n) return;

    const uint4* S = (const uint4*)g_hs2;
    float a[8];
#pragma unroll
    for (int j = 0; j < 8; j++) a[j] = 0.0f;
    acc_msg(a, S[(size_t)i * 2 + p]);
    int cnt = g_cnt[i];
    int cn  = min(cnt, MAXD);
    pair_gather(S, a, &g_adj[(size_t)i << 6], cn, p);
    if (cnt > MAXD) ovf_fixup(S, a, i, p);

    float d = rsqrtf((float)(cnt + 1));
    const float* bb = b2 + p * 8;
    const float* ww = Wl + p * 8;
    float s = 0.0f;
#pragma unroll
    for (int j = 0; j < 8; j++)
        s += fmaxf(d * a[j] + __ldg(&bb[j]), 0.0f) * __ldg(&ww[j]);

    unsigned lane = threadIdx.x & 31u;
    unsigned pm = 0x3u << (lane & ~1u);
    s += __shfl_xor_sync(pm, s, 1, 2);
    if (p == 0) out[i] = s + __ldg(bl);
}

// ---------------- launch ----------------

extern "C" void kernel_launch(void* const* d_in, const int* in_sizes, int n_in,
                              void* d_out, int out_size) {
    const float* x   = (const float*)d_in[0];
    const int*   ei  = (const int*)  d_in[1];
    const float* W1  = (const float*)d_in[2];
    const float* b1  = (const float*)d_in[3];
    const float* W2  = (const float*)d_in[4];
    const float* b2  = (const float*)d_in[5];
    const float* Wl  = (const float*)d_in[6];
    const float* bl  = (const float*)d_in[7];
    float* out = (float*)d_out;

    const int n = in_sizes[0] / IN_CH;   // 100000
    const int e = in_sizes[1] / 2;       // 3200000
    const int* row = ei;
    const int* col = ei + e;

    const int TB = 256;
    const int gn = (n + TB - 1) / TB;
    const int n4 = n / 4;
    const int e4 = e / 4;
    const int gp = (n * 2 + TB - 1) / TB;

    // build (single pass)
    k_zero <<<(n4 + TB - 1) / TB, TB>>>(n4);
    k_build<<<(e4 + TB - 1) / TB, TB>>>(row, col, e4);

    // layer 1 (+ fused layer-2 transform)
    k_mm1       <<<gn, TB>>>(x, W1, n);
    k_gather_mid<<<gp, TB>>>(W2, b1, n);

    // layer 2 (+ fused readout)
    k_gather_final<<<gp, TB>>>(b2, Wl, bl, out, n);
}

// round 11
// speedup vs baseline: 1.9474x; 1.0927x over previous
#include <cuda_runtime.h>
#include <cuda_fp16.h>
#include <cuda_bf16.h>

#define N_NODES 100000
#define N_EDGES 3200000
#define IN_CH   128
#define HID     16
#define MAXD    64            // fixed adjacency stride; overflow handled exactly
#define OVF_MAX 4096

// ---------------- device scratch (no allocation allowed) ----------------
__device__ __align__(16) int    g_cnt[N_NODES];
__device__ __align__(16) int    g_adj[N_NODES * MAXD];   // 25.6 MB fixed-stride adjacency
__device__ int                  g_ovf_cnt;
__device__ __align__(16) int    g_ovf[2 * OVF_MAX];      // (col,row) overflow pairs
__device__ __align__(16) __half g_hs [N_NODES * HID];    // layer-1 messages (fp16)
__device__ __align__(16) __half g_hs2[N_NODES * HID];    // layer-2 messages (fp16)

__device__ __forceinline__ unsigned h2u(__half2 h) {
    return *reinterpret_cast<unsigned*>(&h);
}

// ---------------- build ----------------

__global__ void k_zero(int n4) {
    int i = blockIdx.x * blockDim.x + threadIdx.x;
    if (i < n4) ((int4*)g_cnt)[i] = make_int4(0, 0, 0, 0);
    if (i == 0) g_ovf_cnt = 0;
}

// single-pass adjacency build; atomic return value doubles as degree histogram
__global__ void k_build(const int* __restrict__ row, const int* __restrict__ col, int e4) {
    int i = blockIdx.x * blockDim.x + threadIdx.x;
    if (i >= e4) return;
    int4 r = __ldg(&((const int4*)row)[i]);
    int4 c = __ldg(&((const int4*)col)[i]);
#pragma unroll
    for (int u = 0; u < 4; u++) {
        int cc = (u == 0) ? c.x : (u == 1) ? c.y : (u == 2) ? c.z : c.w;
        int rr = (u == 0) ? r.x : (u == 1) ? r.y : (u == 2) ? r.z : r.w;
        int p = atomicAdd(&g_cnt[cc], 1);
        if (p < MAXD) {
            g_adj[(cc << 6) + p] = rr;
        } else {
            int o = atomicAdd(&g_ovf_cnt, 1);
            if (o < OVF_MAX) { g_ovf[2 * o] = cc; g_ovf[2 * o + 1] = rr; }
        }
    }
}

// ---------------- compute ----------------

// hs = fp16( dinv * (x @ W1) )   — R6/R10-proven version
__global__ void k_mm1(const float* __restrict__ x, const float* __restrict__ W1, int n) {
    __shared__ float4 Ws[IN_CH * HID / 4];
    for (int t = threadIdx.x; t < IN_CH * HID / 4; t += blockDim.x)
        Ws[t] = ((const float4*)W1)[t];
    __syncthreads();

    int i = blockIdx.x * blockDim.x + threadIdx.x;
    if (i >= n) return;

    float a[HID];
#pragma unroll
    for (int j = 0; j < HID; j++) a[j] = 0.0f;

    const float4* xr = (const float4*)(x + (size_t)i * IN_CH);
#pragma unroll 8
    for (int k4 = 0; k4 < IN_CH / 4; k4++) {
        float4 xv = xr[k4];
        float xs[4] = {xv.x, xv.y, xv.z, xv.w};
#pragma unroll
        for (int r = 0; r < 4; r++) {
            const float4* w = &Ws[(k4 * 4 + r) * 4];
#pragma unroll
            for (int q = 0; q < 4; q++) {
                float4 wv = w[q];
                a[4 * q + 0] += xs[r] * wv.x;
                a[4 * q + 1] += xs[r] * wv.y;
                a[4 * q + 2] += xs[r] * wv.z;
                a[4 * q + 3] += xs[r] * wv.w;
            }
        }
    }

    float d = rsqrtf((float)(g_cnt[i] + 1));
    uint4 pack[2];
    __half2* hp = (__half2*)pack;
#pragma unroll
    for (int j = 0; j < 8; j++)
        hp[j] = __floats2half2_rn(d * a[2 * j], d * a[2 * j + 1]);
    ((uint4*)g_hs)[(size_t)i * 2 + 0] = pack[0];
    ((uint4*)g_hs)[(size_t)i * 2 + 1] = pack[1];
}

// accumulate one fp16x8 message into fp32 acc[8]
__device__ __forceinline__ void acc_msg(float* a, uint4 v) {
    const __half2* h = reinterpret_cast<const __half2*>(&v);
#pragma unroll
    for (int t = 0; t < 4; t++) {
        float2 f = __half22float2(h[t]);
        a[2 * t]     += f.x;
        a[2 * t + 1] += f.y;
    }
}

// gather a[8] over adjacency slots [k, end) for feature half pp
__device__ __forceinline__ void seg_gather(const uint4* __restrict__ S,
                                           float* a, const int* __restrict__ adj,
                                           int k, int end, int pp) {
    if (k + 8 <= end) {
        int r[8];
#pragma unroll
        for (int u = 0; u < 8; u++) r[u] = __ldg(&adj[k + u]);
        k += 8;
        while (k + 8 <= end) {
            int rn[8];
#pragma unroll
            for (int u = 0; u < 8; u++) rn[u] = __ldg(&adj[k + u]);
            uint4 v[8];
#pragma unroll
            for (int u = 0; u < 8; u++) v[u] = S[(size_t)r[u] * 2 + pp];
#pragma unroll
            for (int u = 0; u < 8; u++) acc_msg(a, v[u]);
#pragma unroll
            for (int u = 0; u < 8; u++) r[u] = rn[u];
            k += 8;
        }
        uint4 v[8];
#pragma unroll
        for (int u = 0; u < 8; u++) v[u] = S[(size_t)r[u] * 2 + pp];
#pragma unroll
        for (int u = 0; u < 8; u++) acc_msg(a, v[u]);
    }
    for (; k < end; k++) {
        uint4 v = S[(size_t)__ldg(&adj[k]) * 2 + pp];
        acc_msg(a, v);
    }
}

// exact overflow fixup (overflow list is ≈always empty)
__device__ __forceinline__ void ovf_fixup(const uint4* __restrict__ S,
                                          float* a, int i, int pp) {
    int no = min(g_ovf_cnt, OVF_MAX);
    for (int o = 0; o < no; o++) {
        if (g_ovf[2 * o] == i) {
            uint4 v = S[(size_t)g_ovf[2 * o + 1] * 2 + pp];
            acc_msg(a, v);
        }
    }
}

// 4-lane node gather front-end: pp = feature half, seg = edge-range half.
// Returns full a[8] in all 4 lanes (after seg allreduce).
__device__ __forceinline__ void node_gather4(const uint4* __restrict__ S,
                                             float* a, int i, int cnt,
                                             int pp, int seg, unsigned qmask) {
#pragma unroll
    for (int j = 0; j < 8; j++) a[j] = 0.0f;

    int cn  = min(cnt, MAXD);
    int mid = cn >> 1;
    int k0  = seg ? mid : 0;
    int k1  = seg ? cn  : mid;

    if (seg == 0) acc_msg(a, S[(size_t)i * 2 + pp]);   // self-loop once
    seg_gather(S, a, &g_adj[(size_t)i << 6], k0, k1, pp);
    if (seg == 1 && cnt > MAXD) ovf_fixup(S, a, i, pp);

    // allreduce across the two segments (xor 2 flips seg, keeps pp)
#pragma unroll
    for (int j = 0; j < 8; j++)
        a[j] += __shfl_xor_sync(qmask, a[j], 2, 4);
}

// gather layer-1 + fused: h1 = relu(d*a + b1); hs2 = fp16(d*(h1 @ W2))
__global__ void k_gather_mid(const float* __restrict__ W2, const float* __restrict__ b1, int n) {
    __shared__ float Ws[HID * HID];
    if (threadIdx.x < HID * HID / 4)
        ((float4*)Ws)[threadIdx.x] = ((const float4*)W2)[threadIdx.x];
    __syncthreads();

    int gid = blockIdx.x * blockDim.x + threadIdx.x;
    int i   = gid >> 2;
    int pp  = gid & 1;
    int seg = (gid >> 1) & 1;
    if (i >= n) return;

    unsigned lane = threadIdx.x & 31u;
    unsigned qmask = 0xFu << (lane & ~3u);

    const uint4* S = (const uint4*)g_hs;
    float a[8];
    int cnt = g_cnt[i];
    node_gather4(S, a, i, cnt, pp, seg, qmask);

    float d = rsqrtf((float)(cnt + 1));
    float h8[8];
    const float* bb = b1 + pp * 8;
#pragma unroll
    for (int j = 0; j < 8; j++)
        h8[j] = fmaxf(d * a[j] + __ldg(&bb[j]), 0.0f);

    // exchange halves across pp (xor 1 flips pp, keeps seg)
    float hall[HID];
#pragma unroll
    for (int j = 0; j < 8; j++) hall[pp * 8 + j] = h8[j];
#pragma unroll
    for (int j = 0; j < 8; j++)
        hall[(pp ^ 1) * 8 + j] = __shfl_xor_sync(qmask, h8[j], 1, 4);

    float t[8];
#pragma unroll
    for (int j = 0; j < 8; j++) t[j] = 0.0f;
#pragma unroll
    for (int k = 0; k < HID; k++) {
        float hk = hall[k];
        const float* w = &Ws[k * HID + pp * 8];
#pragma unroll
        for (int j = 0; j < 8; j++) t[j] += hk * w[j];
    }

    if (seg == 0) {
        uint4 pack;
        __half2* hp = (__half2*)&pack;
#pragma unroll
        for (int j = 0; j < 4; j++)
            hp[j] = __floats2half2_rn(d * t[2 * j], d * t[2 * j + 1]);
        ((uint4*)g_hs2)[(size_t)i * 2 + pp] = pack;
    }
}

// gather layer-2 + fused readout: out = relu(d*a + b2) . Wl + bl
__global__ void k_gather_final(const float* __restrict__ b2, const float* __restrict__ Wl,
                               const float* __restrict__ bl, float* __restrict__ out, int n) {
    int gid = blockIdx.x * blockDim.x + threadIdx.x;
    int i   = gid >> 2;
    int pp  = gid & 1;
    int seg = (gid >> 1) & 1;
    if (i >= n) return;

    unsigned lane = threadIdx.x & 31u;
    unsigned qmask = 0xFu << (lane & ~3u);

    const uint4* S = (const uint4*)g_hs2;
    float a[8];
    int cnt = g_cnt[i];
    node_gather4(S, a, i, cnt, pp, seg, qmask);

    float d = rsqrtf((float)(cnt + 1));
    const float* bb = b2 + pp * 8;
    const float* ww = Wl + pp * 8;
    float s = 0.0f;
#pragma unroll
    for (int j = 0; j < 8; j++)
        s += fmaxf(d * a[j] + __ldg(&bb[j]), 0.0f) * __ldg(&ww[j]);

    // reduce across pp (xor 1); all 4 lanes converge, lane (pp==0,seg==0) writes
    s += __shfl_xor_sync(qmask, s, 1, 4);
    if (pp == 0 && seg == 0) out[i] = s + __ldg(bl);
}

// ---------------- launch ----------------

extern "C" void kernel_launch(void* const* d_in, const int* in_sizes, int n_in,
                              void* d_out, int out_size) {
    const float* x   = (const float*)d_in[0];
    const int*   ei  = (const int*)  d_in[1];
    const float* W1  = (const float*)d_in[2];
    const float* b1  = (const float*)d_in[3];
    const float* W2  = (const float*)d_in[4];
    const float* b2  = (const float*)d_in[5];
    const float* Wl  = (const float*)d_in[6];
    const float* bl  = (const float*)d_in[7];
    float* out = (float*)d_out;

    const int n = in_sizes[0] / IN_CH;   // 100000
    const int e = in_sizes[1] / 2;       // 3200000
    const int* row = ei;
    const int* col = ei + e;

    const int TB = 256;
    const int gn = (n + TB - 1) / TB;
    const int n4 = n / 4;
    const int e4 = e / 4;
    const int gq = (n * 4 + TB - 1) / TB;

    // build (single pass)
    k_zero <<<(n4 + TB - 1) / TB, TB>>>(n4);
    k_build<<<(e4 + TB - 1) / TB, TB>>>(row, col, e4);

    // layer 1 (+ fused layer-2 transform)
    k_mm1       <<<gn, TB>>>(x, W1, n);
    k_gather_mid<<<gq, TB>>>(W2, b1, n);

    // layer 2 (+ fused readout)
    k_gather_final<<<gq, TB>>>(b2, Wl, bl, out, n);
}

// round 12
// speedup vs baseline: 1.9515x; 1.0021x over previous
#include <cuda_runtime.h>
#include <cuda_fp16.h>
#include <cuda_bf16.h>

#define N_NODES 100000
#define N_EDGES 3200000
#define IN_CH   128
#define HID     16
#define MAXD    64            // fixed adjacency stride; overflow handled exactly
#define OVF_MAX 4096

// ---------------- device scratch (no allocation allowed) ----------------
__device__ __align__(16) int    g_cnt[N_NODES];
__device__ __align__(16) int    g_adj[N_NODES * MAXD];   // 25.6 MB fixed-stride adjacency
__device__ int                  g_ovf_cnt;
__device__ __align__(16) int    g_ovf[2 * OVF_MAX];      // (col,row) overflow pairs
__device__ __align__(16) __half g_hs [N_NODES * HID];    // layer-1 messages (fp16)
__device__ __align__(16) __half g_hs2[N_NODES * HID];    // layer-2 messages (fp16)

__device__ __forceinline__ unsigned h2u(__half2 h) {
    return *reinterpret_cast<unsigned*>(&h);
}

// ---------------- build ----------------

__global__ void k_zero(int n4) {
    int i = blockIdx.x * blockDim.x + threadIdx.x;
    if (i < n4) ((int4*)g_cnt)[i] = make_int4(0, 0, 0, 0);
    if (i == 0) g_ovf_cnt = 0;
}

// single-pass adjacency build; atomic return value doubles as degree histogram
__global__ void k_build(const int* __restrict__ row, const int* __restrict__ col, int e4) {
    int i = blockIdx.x * blockDim.x + threadIdx.x;
    if (i >= e4) return;
    int4 r = __ldg(&((const int4*)row)[i]);
    int4 c = __ldg(&((const int4*)col)[i]);
#pragma unroll
    for (int u = 0; u < 4; u++) {
        int cc = (u == 0) ? c.x : (u == 1) ? c.y : (u == 2) ? c.z : c.w;
        int rr = (u == 0) ? r.x : (u == 1) ? r.y : (u == 2) ? r.z : r.w;
        int p = atomicAdd(&g_cnt[cc], 1);
        if (p < MAXD) {
            g_adj[(cc << 6) + p] = rr;
        } else {
            int o = atomicAdd(&g_ovf_cnt, 1);
            if (o < OVF_MAX) { g_ovf[2 * o] = cc; g_ovf[2 * o + 1] = rr; }
        }
    }
}

// ---------------- compute ----------------

// hs = fp16( dinv * (x @ W1) )
__global__ void k_mm1(const float* __restrict__ x, const float* __restrict__ W1, int n) {
    __shared__ float4 Ws[IN_CH * HID / 4];
    for (int t = threadIdx.x; t < IN_CH * HID / 4; t += blockDim.x)
        Ws[t] = ((const float4*)W1)[t];
    __syncthreads();

    int i = blockIdx.x * blockDim.x + threadIdx.x;
    if (i >= n) return;

    float a[HID];
#pragma unroll
    for (int j = 0; j < HID; j++) a[j] = 0.0f;

    const float4* xr = (const float4*)(x + (size_t)i * IN_CH);
#pragma unroll 8
    for (int k4 = 0; k4 < IN_CH / 4; k4++) {
        float4 xv = xr[k4];
        float xs[4] = {xv.x, xv.y, xv.z, xv.w};
#pragma unroll
        for (int r = 0; r < 4; r++) {
            const float4* w = &Ws[(k4 * 4 + r) * 4];
#pragma unroll
            for (int q = 0; q < 4; q++) {
                float4 wv = w[q];
                a[4 * q + 0] += xs[r] * wv.x;
                a[4 * q + 1] += xs[r] * wv.y;
                a[4 * q + 2] += xs[r] * wv.z;
                a[4 * q + 3] += xs[r] * wv.w;
            }
        }
    }

    float d = rsqrtf((float)(g_cnt[i] + 1));
    uint4 pack[2];
    __half2* hp = (__half2*)pack;
#pragma unroll
    for (int j = 0; j < 8; j++)
        hp[j] = __floats2half2_rn(d * a[2 * j], d * a[2 * j + 1]);
    ((uint4*)g_hs)[(size_t)i * 2 + 0] = pack[0];
    ((uint4*)g_hs)[(size_t)i * 2 + 1] = pack[1];
}

// accumulate one fp16x8 message into fp32 acc[8]
__device__ __forceinline__ void acc_msg(float* a, uint4 v) {
    const __half2* h = reinterpret_cast<const __half2*>(&v);
#pragma unroll
    for (int t = 0; t < 4; t++) {
        float2 f = __half22float2(h[t]);
        a[2 * t]     += f.x;
        a[2 * t + 1] += f.y;
    }
}

// gather a[8] over adjacency slots [k, end), k multiple of 4; int4 index loads
__device__ __forceinline__ void seg_gather(const uint4* __restrict__ S,
                                           float* a, const int* __restrict__ adj,
                                           int k, int end, int pp) {
    const int4* adj4 = (const int4*)adj;   // adj row is 256B aligned; k % 4 == 0

    // 8-wide software-pipelined main loop (2 int4 index loads per iteration)
    if (k + 8 <= end) {
        int4 ra = __ldg(&adj4[k >> 2]);
        int4 rb = __ldg(&adj4[(k >> 2) + 1]);
        k += 8;
        while (k + 8 <= end) {
            int4 na = __ldg(&adj4[k >> 2]);
            int4 nb = __ldg(&adj4[(k >> 2) + 1]);
            uint4 v[8];
            v[0] = S[(size_t)ra.x * 2 + pp];
            v[1] = S[(size_t)ra.y * 2 + pp];
            v[2] = S[(size_t)ra.z * 2 + pp];
            v[3] = S[(size_t)ra.w * 2 + pp];
            v[4] = S[(size_t)rb.x * 2 + pp];
            v[5] = S[(size_t)rb.y * 2 + pp];
            v[6] = S[(size_t)rb.z * 2 + pp];
            v[7] = S[(size_t)rb.w * 2 + pp];
#pragma unroll
            for (int u = 0; u < 8; u++) acc_msg(a, v[u]);
            ra = na; rb = nb;
            k += 8;
        }
        uint4 v[8];
        v[0] = S[(size_t)ra.x * 2 + pp];
        v[1] = S[(size_t)ra.y * 2 + pp];
        v[2] = S[(size_t)ra.z * 2 + pp];
        v[3] = S[(size_t)ra.w * 2 + pp];
        v[4] = S[(size_t)rb.x * 2 + pp];
        v[5] = S[(size_t)rb.y * 2 + pp];
        v[6] = S[(size_t)rb.z * 2 + pp];
        v[7] = S[(size_t)rb.w * 2 + pp];
#pragma unroll
        for (int u = 0; u < 8; u++) acc_msg(a, v[u]);
    }

    // 4-wide step
    if (k + 4 <= end) {
        int4 ra = __ldg(&adj4[k >> 2]);
        uint4 v0 = S[(size_t)ra.x * 2 + pp];
        uint4 v1 = S[(size_t)ra.y * 2 + pp];
        uint4 v2 = S[(size_t)ra.z * 2 + pp];
        uint4 v3 = S[(size_t)ra.w * 2 + pp];
        acc_msg(a, v0); acc_msg(a, v1); acc_msg(a, v2); acc_msg(a, v3);
        k += 4;
    }

    // scalar tail
    for (; k < end; k++) {
        uint4 v = S[(size_t)__ldg(&adj[k]) * 2 + pp];
        acc_msg(a, v);
    }
}

// exact overflow fixup (overflow list is ≈always empty)
__device__ __forceinline__ void ovf_fixup(const uint4* __restrict__ S,
                                          float* a, int i, int pp) {
    int no = min(g_ovf_cnt, OVF_MAX);
    for (int o = 0; o < no; o++) {
        if (g_ovf[2 * o] == i) {
            uint4 v = S[(size_t)g_ovf[2 * o + 1] * 2 + pp];
            acc_msg(a, v);
        }
    }
}

// 4-lane node gather front-end: pp = feature half, seg = edge-range half.
// Returns full a[8] in all 4 lanes (after seg allreduce).
__device__ __forceinline__ void node_gather4(const uint4* __restrict__ S,
                                             float* a, int i, int cnt,
                                             int pp, int seg, unsigned qmask) {
#pragma unroll
    for (int j = 0; j < 8; j++) a[j] = 0.0f;

    int cn  = min(cnt, MAXD);
    int mid = min(cn, ((cn >> 1) + 3) & ~3);   // 4-aligned split point
    int k0  = seg ? mid : 0;
    int k1  = seg ? cn  : mid;

    if (seg == 0) acc_msg(a, S[(size_t)i * 2 + pp]);   // self-loop once
    seg_gather(S, a, &g_adj[(size_t)i << 6], k0, k1, pp);
    if (seg == 1 && cnt > MAXD) ovf_fixup(S, a, i, pp);

    // allreduce across the two segments (xor 2 flips seg, keeps pp)
#pragma unroll
    for (int j = 0; j < 8; j++)
        a[j] += __shfl_xor_sync(qmask, a[j], 2, 4);
}

// gather layer-1 + fused: h1 = relu(d*a + b1); hs2 = fp16(d*(h1 @ W2))
__global__ void k_gather_mid(const float* __restrict__ W2, const float* __restrict__ b1, int n) {
    __shared__ float Ws[HID * HID];
    if (threadIdx.x < HID * HID / 4)
        ((float4*)Ws)[threadIdx.x] = ((const float4*)W2)[threadIdx.x];
    __syncthreads();

    int gid = blockIdx.x * blockDim.x + threadIdx.x;
    int i   = gid >> 2;
    int pp  = gid & 1;
    int seg = (gid >> 1) & 1;
    if (i >= n) return;

    unsigned lane = threadIdx.x & 31u;
    unsigned qmask = 0xFu << (lane & ~3u);

    const uint4* S = (const uint4*)g_hs;
    float a[8];
    int cnt = g_cnt[i];
    node_gather4(S, a, i, cnt, pp, seg, qmask);

    float d = rsqrtf((float)(cnt + 1));
    float h8[8];
    const float* bb = b1 + pp * 8;
#pragma unroll
    for (int j = 0; j < 8; j++)
        h8[j] = fmaxf(d * a[j] + __ldg(&bb[j]), 0.0f);

    // exchange halves across pp (xor 1 flips pp, keeps seg)
    float hall[HID];
#pragma unroll
    for (int j = 0; j < 8; j++) hall[pp * 8 + j] = h8[j];
#pragma unroll
    for (int j = 0; j < 8; j++)
        hall[(pp ^ 1) * 8 + j] = __shfl_xor_sync(qmask, h8[j], 1, 4);

    float t[8];
#pragma unroll
    for (int j = 0; j < 8; j++) t[j] = 0.0f;
#pragma unroll
    for (int k = 0; k < HID; k++) {
        float hk = hall[k];
        const float* w = &Ws[k * HID + pp * 8];
#pragma unroll
        for (int j = 0; j < 8; j++) t[j] += hk * w[j];
    }

    if (seg == 0) {
        uint4 pack;
        __half2* hp = (__half2*)&pack;
#pragma unroll
        for (int j = 0; j < 4; j++)
            hp[j] = __floats2half2_rn(d * t[2 * j], d * t[2 * j + 1]);
        ((uint4*)g_hs2)[(size_t)i * 2 + pp] = pack;
    }
}

// gather layer-2 + fused readout: out = relu(d*a + b2) . Wl + bl
__global__ void k_gather_final(const float* __restrict__ b2, const float* __restrict__ Wl,
                               const float* __restrict__ bl, float* __restrict__ out, int n) {
    int gid = blockIdx.x * blockDim.x + threadIdx.x;
    int i   = gid >> 2;
    int pp  = gid & 1;
    int seg = (gid >> 1) & 1;
    if (i >= n) return;

    unsigned lane = threadIdx.x & 31u;
    unsigned qmask = 0xFu << (lane & ~3u);

    const uint4* S = (const uint4*)g_hs2;
    float a[8];
    int cnt = g_cnt[i];
    node_gather4(S, a, i, cnt, pp, seg, qmask);

    float d = rsqrtf((float)(cnt + 1));
    const float* bb = b2 + pp * 8;
    const float* ww = Wl + pp * 8;
    float s = 0.0f;
#pragma unroll
    for (int j = 0; j < 8; j++)
        s += fmaxf(d * a[j] + __ldg(&bb[j]), 0.0f) * __ldg(&ww[j]);

    // reduce across pp (xor 1); lane (pp==0,seg==0) writes
    s += __shfl_xor_sync(qmask, s, 1, 4);
    if (pp == 0 && seg == 0) out[i] = s + __ldg(bl);
}

// ---------------- launch ----------------

extern "C" void kernel_launch(void* const* d_in, const int* in_sizes, int n_in,
                              void* d_out, int out_size) {
    const float* x   = (const float*)d_in[0];
    const int*   ei  = (const int*)  d_in[1];
    const float* W1  = (const float*)d_in[2];
    const float* b1  = (const float*)d_in[3];
    const float* W2  = (const float*)d_in[4];
    const float* b2  = (const float*)d_in[5];
    const float* Wl  = (const float*)d_in[6];
    const float* bl  = (const float*)d_in[7];
    float* out = (float*)d_out;

    const int n = in_sizes[0] / IN_CH;   // 100000
    const int e = in_sizes[1] / 2;       // 3200000
    const int* row = ei;
    const int* col = ei + e;

    const int TB = 256;
    const int gn = (n + TB - 1) / TB;
    const int n4 = n / 4;
    const int e4 = e / 4;
    const int gq = (n * 4 + TB - 1) / TB;

    // build (single pass)
    k_zero <<<(n4 + TB - 1) / TB, TB>>>(n4);
    k_build<<<(e4 + TB - 1) / TB, TB>>>(row, col, e4);

    // layer 1 (+ fused layer-2 transform)
    k_mm1       <<<gn, TB>>>(x, W1, n);
    k_gather_mid<<<gq, TB>>>(W2, b1, n);

    // layer 2 (+ fused readout)
    k_gather_final<<<gq, TB>>>(b2, Wl, bl, out, n);
}